// round 7
// baseline (speedup 1.0000x reference)
#include <cuda_runtime.h>

// Problem constants (fixed by setup_inputs): B=8, N=20, K=5, Q=15, D=1024
#define BB     8
#define NN     20
#define KSUP   5
#define QQ     15
#define DD     1024
#define ROWS   (KSUP + QQ)        // 20 rows per (b,n)
#define NQ     (NN * QQ)          // 300 queries per batch
#define NQTOT  (BB * NQ)          // 2400 queries total
#define WARPS  16
#define THREADS 512
#define GRID   (NQTOT / WARPS)    // 150 blocks, 1 query/warp, single wave

// ---------------------------------------------------------------------------
// Single fused kernel: 150 blocks x 512 threads (16 warps), 1 block/SM,
// one query per warp, single wave.
//   Phase 1 (fill): compute proto tile for this block's batch directly into
//     smem (mean of 5 support rows, read from emb with MLP=5, L2-resident).
//   Phase 2: term_p[n] = proto[n] . w0 from smem (16 warps cover 20 dots).
//   Phase 3: per-warp query regs (q, q*w3, folded term_q), then the FFMA
//     loop: all 20 n-accumulators in regs, two passes of 10; deferred
//     independent shfl butterflies; lane 0 writes final logits.
// ---------------------------------------------------------------------------
__global__ __launch_bounds__(THREADS, 1) void relnet_fused_kernel(
    const float* __restrict__ emb,
    const float* __restrict__ weight,
    const float* __restrict__ bias,
    float* __restrict__ out)
{
    extern __shared__ float smem[];
    float4* sP4 = reinterpret_cast<float4*>(smem);               // 20*256 f4 = 81920 B
    float4* sW2 = reinterpret_cast<float4*>(smem + NN * DD);     // 256 f4    =  4096 B
    float*  sTp = smem + NN * DD + 1024;                         // 20 floats

    const int tid  = threadIdx.x;
    const int lane = tid & 31;
    const int warp = tid >> 5;

    const int g   = blockIdx.x * WARPS + warp;   // global query id 0..2399
    const int bMy = g / NQ;
    const int q   = g - bMy * NQ;                // query idx within batch
    const int bLo = (blockIdx.x * WARPS) / NQ;
    const int bHi = (blockIdx.x * WARPS + WARPS - 1) / NQ;

    const float4* emb4 = reinterpret_cast<const float4*>(emb);
    const float4* w04  = reinterpret_cast<const float4*>(weight);
    const float4* w14  = w04 + 1 * 256;
    const float4* w24  = w04 + 2 * 256;
    const float4* w34  = w04 + 3 * 256;
    const float bi = bias[0];

    // ---- per-warp query registers: q and q*w3; fold term_q ----
    const int qrow = (bMy * NN + q / QQ) * ROWS + KSUP + q % QQ;
    const float4* r = emb4 + (size_t)qrow * 256;

    float qv[32], cv[32];
    float tq = 0.f;
#pragma unroll
    for (int i = 0; i < 8; i++) {
        const int idx = i * 32 + lane;
        float4 a  = r[idx];
        float4 w3 = w34[idx];
        float4 w1 = w14[idx];
        qv[4*i+0] = a.x; qv[4*i+1] = a.y; qv[4*i+2] = a.z; qv[4*i+3] = a.w;
        cv[4*i+0] = a.x * w3.x; cv[4*i+1] = a.y * w3.y;
        cv[4*i+2] = a.z * w3.z; cv[4*i+3] = a.w * w3.w;
        tq = fmaf(a.x, w1.x, tq); tq = fmaf(a.y, w1.y, tq);
        tq = fmaf(a.z, w1.z, tq); tq = fmaf(a.w, w1.w, tq);
    }
#pragma unroll
    for (int off = 16; off; off >>= 1) tq += __shfl_xor_sync(0xFFFFFFFFu, tq, off);

    float* o = out + ((size_t)bMy * NQ + q) * NN;

#pragma unroll 1
    for (int b = bLo; b <= bHi; b++) {
        // ---- Phase 1: build proto tile in smem (mean of KSUP support rows) ----
        __syncthreads();   // protect smem from previous iteration's readers
#pragma unroll 1
        for (int idx = tid; idx < NN * 256; idx += THREADS) {
            const int n = idx >> 8;          // 0..19
            const int c = idx & 255;         // float4 column
            const float4* sup = emb4 + ((size_t)(b * NN + n) * ROWS) * 256 + c;
            float4 s = sup[0];
            float4 v1 = sup[256], v2 = sup[512], v3 = sup[768], v4 = sup[1024];
            s.x += v1.x; s.y += v1.y; s.z += v1.z; s.w += v1.w;
            s.x += v2.x; s.y += v2.y; s.z += v2.z; s.w += v2.w;
            s.x += v3.x; s.y += v3.y; s.z += v3.z; s.w += v3.w;
            s.x += v4.x; s.y += v4.y; s.z += v4.z; s.w += v4.w;
            s.x *= 0.2f; s.y *= 0.2f; s.z *= 0.2f; s.w *= 0.2f;
            sP4[idx] = s;
        }
        if (tid < 256) sW2[tid] = w24[tid];
        __syncthreads();

        // ---- Phase 2: term_p[n] = proto[n] . w0 (warps 0..15 cover n, then n+16) ----
#pragma unroll 1
        for (int n = warp; n < NN; n += WARPS) {
            const float4* pr = sP4 + n * 256;
            float tp = 0.f;
#pragma unroll
            for (int i = 0; i < 8; i++) {
                const int idx = i * 32 + lane;
                float4 p  = pr[idx];
                float4 w0 = w04[idx];
                tp = fmaf(p.x, w0.x, tp); tp = fmaf(p.y, w0.y, tp);
                tp = fmaf(p.z, w0.z, tp); tp = fmaf(p.w, w0.w, tp);
            }
#pragma unroll
            for (int off = 16; off; off >>= 1) tp += __shfl_xor_sync(0xFFFFFFFFu, tp, off);
            if (lane == 0) sTp[n] = tp;
        }
        __syncthreads();

        if (bMy != b) continue;

        // ---- Phase 3: main FFMA loop, two passes of 10 n-accumulators ----
#pragma unroll 1
        for (int pass = 0; pass < 2; pass++) {
            float acc[10];
#pragma unroll
            for (int n = 0; n < 10; n++) acc[n] = 0.f;

            const float4* pb = sP4 + pass * 10 * 256 + lane;
#pragma unroll
            for (int i = 0; i < 8; i++) {
                const float4 w2 = sW2[i * 32 + lane];
#pragma unroll
                for (int n = 0; n < 10; n++) {
                    const float4 p = pb[n * 256 + i * 32];
                    acc[n] = fmaf(fabsf(p.x - qv[4*i+0]), w2.x, acc[n]);
                    acc[n] = fmaf(p.x, cv[4*i+0], acc[n]);
                    acc[n] = fmaf(fabsf(p.y - qv[4*i+1]), w2.y, acc[n]);
                    acc[n] = fmaf(p.y, cv[4*i+1], acc[n]);
                    acc[n] = fmaf(fabsf(p.z - qv[4*i+2]), w2.z, acc[n]);
                    acc[n] = fmaf(p.z, cv[4*i+2], acc[n]);
                    acc[n] = fmaf(fabsf(p.w - qv[4*i+3]), w2.w, acc[n]);
                    acc[n] = fmaf(p.w, cv[4*i+3], acc[n]);
                }
            }

            // deferred reductions: 10 independent butterflies
#pragma unroll
            for (int n = 0; n < 10; n++) {
                float s = acc[n];
#pragma unroll
                for (int off = 16; off; off >>= 1)
                    s += __shfl_xor_sync(0xFFFFFFFFu, s, off);
                acc[n] = s;
            }
            if (lane == 0) {
#pragma unroll
                for (int n = 0; n < 10; n++) {
                    const int nn = pass * 10 + n;
                    o[nn] = acc[n] + sTp[nn] + tq + bi;
                }
            }
        }
    }
}

// ---------------------------------------------------------------------------
// Launch: ONE kernel, one wave.
// ---------------------------------------------------------------------------
static const int SMEM_BYTES = (NN * DD + 1024 + 32) * (int)sizeof(float); // 86,144 B

extern "C" void kernel_launch(void* const* d_in, const int* in_sizes, int n_in,
                              void* d_out, int out_size)
{
    const float* emb    = (const float*)d_in[0];
    const float* weight = (const float*)d_in[1];
    const float* bias   = (const float*)d_in[2];
    float* out          = (float*)d_out;

    cudaFuncSetAttribute(relnet_fused_kernel,
                         cudaFuncAttributeMaxDynamicSharedMemorySize, SMEM_BYTES);

    relnet_fused_kernel<<<GRID, THREADS, SMEM_BYTES>>>(emb, weight, bias, out);
}

// round 8
// speedup vs baseline: 1.1604x; 1.1604x over previous
#include <cuda_runtime.h>

// Problem constants (fixed by setup_inputs): B=8, N=20, K=5, Q=15, D=1024
#define BB     8
#define NN     20
#define KSUP   5
#define QQ     15
#define DD     1024
#define ROWS   (KSUP + QQ)        // 20 rows per (b,n)
#define NQ     (NN * QQ)          // 300 queries per batch
#define NQTOT  (BB * NQ)          // 2400 queries total
#define WARPS  32
#define THREADS 1024
#define QPB    16                 // queries per block (2 warps per query)
#define GRID   (NQTOT / QPB)      // 150 blocks, single wave

// Scratch (device globals — no allocation allowed)
__device__ float g_proto[BB * NN * DD];   // 640 KB, L2-resident
__device__ float g_termp[BB * NN];

// ---------------------------------------------------------------------------
// K1: proto[b,n,:] = mean_j support, term_p[b,n] = proto . w0  (computed ONCE)
// ---------------------------------------------------------------------------
__global__ __launch_bounds__(256) void proto_kernel(
    const float* __restrict__ emb, const float* __restrict__ weight)
{
    int bn = blockIdx.x;             // b*20 + n
    int t  = threadIdx.x;            // float4 index 0..255
    const float4* base = reinterpret_cast<const float4*>(emb) + (size_t)bn * ROWS * 256;

    float4 s = base[t];
#pragma unroll
    for (int j = 1; j < KSUP; j++) {
        float4 v = base[j * 256 + t];
        s.x += v.x; s.y += v.y; s.z += v.z; s.w += v.w;
    }
    s.x *= 0.2f; s.y *= 0.2f; s.z *= 0.2f; s.w *= 0.2f;
    reinterpret_cast<float4*>(g_proto)[(size_t)bn * 256 + t] = s;

    float4 w0 = reinterpret_cast<const float4*>(weight)[t];
    float tp = s.x * w0.x + s.y * w0.y + s.z * w0.z + s.w * w0.w;
#pragma unroll
    for (int off = 16; off; off >>= 1) tp += __shfl_xor_sync(0xFFFFFFFFu, tp, off);

    __shared__ float red[8];
    if ((t & 31) == 0) red[t >> 5] = tp;
    __syncthreads();
    if (t == 0) {
        float r = 0.f;
#pragma unroll
        for (int w = 0; w < 8; w++) r += red[w];
        g_termp[bn] = r;
    }
}

// ---------------------------------------------------------------------------
// Main: 150 blocks x 1024 threads (32 warps), 1 block/SM, single wave.
// Each query is owned by a WARP PAIR split across D-halves (512 floats each)
// => per-warp state: qv[16]+cv[16]+acc[10] -> fits the 64-reg cap, no spills,
// 8 warps/SMSP for latency hiding. Warp-pair partials combined via smem.
// ---------------------------------------------------------------------------
__global__ __launch_bounds__(THREADS, 1) void relnet_kernel(
    const float* __restrict__ emb,
    const float* __restrict__ weight,
    const float* __restrict__ bias,
    float* __restrict__ out)
{
    extern __shared__ float smem[];
    float4* sP4   = reinterpret_cast<float4*>(smem);               // 20*256 f4 = 81920 B
    float4* sW2   = reinterpret_cast<float4*>(smem + NN * DD);     // 256 f4    =  4096 B
    float*  sTp   = smem + NN * DD + 1024;                         // 20 floats
    float*  sPart = smem + NN * DD + 1024 + 32;                    // 32*20 floats = 2560 B

    const int tid  = threadIdx.x;
    const int lane = tid & 31;
    const int warp = tid >> 5;
    const int half = warp & 1;                 // D-half owned by this warp
    const int qloc = warp >> 1;                // local query 0..15

    const int g   = blockIdx.x * QPB + qloc;   // global query id 0..2399
    const int bMy = g / NQ;
    const int q   = g - bMy * NQ;              // query idx within batch
    const int bLo = (blockIdx.x * QPB) / NQ;
    const int bHi = (blockIdx.x * QPB + QPB - 1) / NQ;

    const float4* emb4 = reinterpret_cast<const float4*>(emb);
    const float4* w14  = reinterpret_cast<const float4*>(weight) + 1 * 256;
    const float4* w24  = reinterpret_cast<const float4*>(weight) + 2 * 256;
    const float4* w34  = reinterpret_cast<const float4*>(weight) + 3 * 256;
    const float4* gP4  = reinterpret_cast<const float4*>(g_proto);
    const float bi = bias[0];

    // ---- per-warp query D-half registers: q and q*w3; fold term_q half ----
    const int qrow = (bMy * NN + q / QQ) * ROWS + KSUP + q % QQ;
    const float4* r = emb4 + (size_t)qrow * 256 + half * 128;

    float qv[16], cv[16];
    float tq = 0.f;
#pragma unroll
    for (int i = 0; i < 4; i++) {
        const int idx = i * 32 + lane;
        float4 a  = r[idx];
        float4 w3 = w34[half * 128 + idx];
        float4 w1 = w14[half * 128 + idx];
        qv[4*i+0] = a.x; qv[4*i+1] = a.y; qv[4*i+2] = a.z; qv[4*i+3] = a.w;
        cv[4*i+0] = a.x * w3.x; cv[4*i+1] = a.y * w3.y;
        cv[4*i+2] = a.z * w3.z; cv[4*i+3] = a.w * w3.w;
        tq = fmaf(a.x, w1.x, tq); tq = fmaf(a.y, w1.y, tq);
        tq = fmaf(a.z, w1.z, tq); tq = fmaf(a.w, w1.w, tq);
    }
#pragma unroll
    for (int off = 16; off; off >>= 1) tq += __shfl_xor_sync(0xFFFFFFFFu, tq, off);

#pragma unroll 1
    for (int b = bLo; b <= bHi; b++) {
        __syncthreads();   // protect smem from previous iteration's readers
        for (int idx = tid; idx < NN * 256; idx += THREADS)
            sP4[idx] = gP4[(size_t)b * NN * 256 + idx];
        if (tid < 256) sW2[tid] = w24[tid];
        if (tid < NN)  sTp[tid] = g_termp[b * NN + tid];
        __syncthreads();
        if (bMy != b) continue;

#pragma unroll 1
        for (int pass = 0; pass < 2; pass++) {
            float acc[10];
#pragma unroll
            for (int n = 0; n < 10; n++) acc[n] = 0.f;

            const float4* pb = sP4 + pass * 10 * 256 + half * 128 + lane;
#pragma unroll
            for (int i = 0; i < 4; i++) {
                const float4 w2 = sW2[half * 128 + i * 32 + lane];
#pragma unroll
                for (int n = 0; n < 10; n++) {
                    const float4 p = pb[n * 256 + i * 32];
                    acc[n] = fmaf(fabsf(p.x - qv[4*i+0]), w2.x, acc[n]);
                    acc[n] = fmaf(p.x, cv[4*i+0], acc[n]);
                    acc[n] = fmaf(fabsf(p.y - qv[4*i+1]), w2.y, acc[n]);
                    acc[n] = fmaf(p.y, cv[4*i+1], acc[n]);
                    acc[n] = fmaf(fabsf(p.z - qv[4*i+2]), w2.z, acc[n]);
                    acc[n] = fmaf(p.z, cv[4*i+2], acc[n]);
                    acc[n] = fmaf(fabsf(p.w - qv[4*i+3]), w2.w, acc[n]);
                    acc[n] = fmaf(p.w, cv[4*i+3], acc[n]);
                }
            }

            // deferred reductions: 10 independent butterflies
#pragma unroll
            for (int n = 0; n < 10; n++) {
                float s = acc[n];
#pragma unroll
                for (int off = 16; off; off >>= 1)
                    s += __shfl_xor_sync(0xFFFFFFFFu, s, off);
                acc[n] = s;
            }
            if (lane == 0) {
#pragma unroll
                for (int n = 0; n < 10; n++) {
                    const int nn = pass * 10 + n;
                    // each half folds its tq half; half 0 also folds tp + bias
                    sPart[warp * NN + nn] = acc[n] + tq
                        + (half == 0 ? sTp[nn] + bi : 0.f);
                }
            }
        }
    }

    // ---- warp-pair combine: out[g, n] = part[2q][n] + part[2q+1][n] ----
    __syncthreads();
    if (tid < QPB * NN) {
        const int ql = tid / NN;
        const int n  = tid - ql * NN;
        const int gq = blockIdx.x * QPB + ql;
        out[(size_t)gq * NN + n] = sPart[(2 * ql) * NN + n] + sPart[(2 * ql + 1) * NN + n];
    }
}

// ---------------------------------------------------------------------------
// Launch
// ---------------------------------------------------------------------------
static const int SMEM_BYTES = (NN * DD + 1024 + 32 + WARPS * NN) * (int)sizeof(float); // 88,704 B

extern "C" void kernel_launch(void* const* d_in, const int* in_sizes, int n_in,
                              void* d_out, int out_size)
{
    const float* emb    = (const float*)d_in[0];
    const float* weight = (const float*)d_in[1];
    const float* bias   = (const float*)d_in[2];
    float* out          = (float*)d_out;

    cudaFuncSetAttribute(relnet_kernel,
                         cudaFuncAttributeMaxDynamicSharedMemorySize, SMEM_BYTES);

    proto_kernel<<<BB * NN, 256>>>(emb, weight);
    relnet_kernel<<<GRID, THREADS, SMEM_BYTES>>>(emb, weight, bias, out);
}

// round 9
// speedup vs baseline: 1.2764x; 1.1000x over previous
#include <cuda_runtime.h>

// Problem constants (fixed by setup_inputs): B=8, N=20, K=5, Q=15, D=1024
#define BB     8
#define NN     20
#define KSUP   5
#define QQ     15
#define DD     1024
#define ROWS   (KSUP + QQ)        // 20 rows per (b,n)
#define NQ     (NN * QQ)          // 300 queries per batch
#define NQTOT  (BB * NQ)          // 2400 queries total
#define NPAIRS (NQTOT / 2)        // 1200 query pairs
#define PAIRS_PER_B (NQ / 2)      // 150
#define WARPS  16
#define THREADS 512
#define PPB    8                  // query-pairs per block (x2 D-halves = 16 warps)
#define GRID   (NPAIRS / PPB)     // 150 blocks, single wave

// Scratch (device globals — no allocation allowed)
__device__ float g_proto[BB * NN * DD];   // 640 KB, L2-resident
__device__ float g_termp[BB * NN];

// ---------------------------------------------------------------------------
// K1: proto[b,n,:] = mean_j support, term_p[b,n] = proto . w0  (computed ONCE)
// ---------------------------------------------------------------------------
__global__ __launch_bounds__(256) void proto_kernel(
    const float* __restrict__ emb, const float* __restrict__ weight)
{
    int bn = blockIdx.x;             // b*20 + n
    int t  = threadIdx.x;            // float4 index 0..255
    const float4* base = reinterpret_cast<const float4*>(emb) + (size_t)bn * ROWS * 256;

    float4 s = base[t];
#pragma unroll
    for (int j = 1; j < KSUP; j++) {
        float4 v = base[j * 256 + t];
        s.x += v.x; s.y += v.y; s.z += v.z; s.w += v.w;
    }
    s.x *= 0.2f; s.y *= 0.2f; s.z *= 0.2f; s.w *= 0.2f;
    reinterpret_cast<float4*>(g_proto)[(size_t)bn * 256 + t] = s;

    float4 w0 = reinterpret_cast<const float4*>(weight)[t];
    float tp = s.x * w0.x + s.y * w0.y + s.z * w0.z + s.w * w0.w;
#pragma unroll
    for (int off = 16; off; off >>= 1) tp += __shfl_xor_sync(0xFFFFFFFFu, tp, off);

    __shared__ float red[8];
    if ((t & 31) == 0) red[t >> 5] = tp;
    __syncthreads();
    if (t == 0) {
        float r = 0.f;
#pragma unroll
        for (int w = 0; w < 8; w++) r += red[w];
        g_termp[bn] = r;
    }
}

// ---------------------------------------------------------------------------
// Main: 150 blocks x 512 threads (16 warps), 1 block/SM, single wave.
// Warp = (query-pair, D-half): each LDS.128 of proto feeds 24 FMA ops
// (both queries) — half the LDS of R4 at the same occupancy and reg budget.
// Partials per D-half combined exactly via smem at the end.
// ---------------------------------------------------------------------------
__global__ __launch_bounds__(THREADS, 1) void relnet_kernel(
    const float* __restrict__ emb,
    const float* __restrict__ weight,
    const float* __restrict__ bias,
    float* __restrict__ out)
{
    extern __shared__ float smem[];
    float4* sP4   = reinterpret_cast<float4*>(smem);               // 20*256 f4 = 81920 B
    float4* sW2   = reinterpret_cast<float4*>(smem + NN * DD);     // 256 f4    =  4096 B
    float*  sTp   = smem + NN * DD + 1024;                         // 20 floats
    float*  sPart = smem + NN * DD + 1024 + 32;                    // 16*40 floats = 2560 B

    const int tid  = threadIdx.x;
    const int lane = tid & 31;
    const int warp = tid >> 5;
    const int half = warp & 1;                     // D-half owned by this warp
    const int pl   = warp >> 1;                    // local pair 0..7

    const int gp   = blockIdx.x * PPB + pl;        // global pair id 0..1199
    const int bMy  = gp / PAIRS_PER_B;
    const int q0   = (gp - bMy * PAIRS_PER_B) * 2; // even query idx in batch
    const int q1   = q0 + 1;
    const int bLo  = (blockIdx.x * PPB) / PAIRS_PER_B;
    const int bHi  = (blockIdx.x * PPB + PPB - 1) / PAIRS_PER_B;

    const float4* emb4 = reinterpret_cast<const float4*>(emb);
    const float4* w14  = reinterpret_cast<const float4*>(weight) + 1 * 256;
    const float4* w24  = reinterpret_cast<const float4*>(weight) + 2 * 256;
    const float4* w34  = reinterpret_cast<const float4*>(weight) + 3 * 256;
    const float4* gP4  = reinterpret_cast<const float4*>(g_proto);
    const float bi = bias[0];

    // ---- per-warp registers: both queries' D-halves (q, q*w3); tq halves ----
    const int r0row = (bMy * NN + q0 / QQ) * ROWS + KSUP + q0 % QQ;
    const int r1row = (bMy * NN + q1 / QQ) * ROWS + KSUP + q1 % QQ;
    const float4* r0 = emb4 + (size_t)r0row * 256 + half * 128;
    const float4* r1 = emb4 + (size_t)r1row * 256 + half * 128;

    float qv0[16], cv0[16], qv1[16], cv1[16];
    float tq0 = 0.f, tq1 = 0.f;
#pragma unroll
    for (int i = 0; i < 4; i++) {
        const int idx = i * 32 + lane;
        float4 a  = r0[idx];
        float4 c  = r1[idx];
        float4 w3 = w34[half * 128 + idx];
        float4 w1 = w14[half * 128 + idx];
        qv0[4*i+0] = a.x; qv0[4*i+1] = a.y; qv0[4*i+2] = a.z; qv0[4*i+3] = a.w;
        qv1[4*i+0] = c.x; qv1[4*i+1] = c.y; qv1[4*i+2] = c.z; qv1[4*i+3] = c.w;
        cv0[4*i+0] = a.x * w3.x; cv0[4*i+1] = a.y * w3.y;
        cv0[4*i+2] = a.z * w3.z; cv0[4*i+3] = a.w * w3.w;
        cv1[4*i+0] = c.x * w3.x; cv1[4*i+1] = c.y * w3.y;
        cv1[4*i+2] = c.z * w3.z; cv1[4*i+3] = c.w * w3.w;
        tq0 = fmaf(a.x, w1.x, tq0); tq0 = fmaf(a.y, w1.y, tq0);
        tq0 = fmaf(a.z, w1.z, tq0); tq0 = fmaf(a.w, w1.w, tq0);
        tq1 = fmaf(c.x, w1.x, tq1); tq1 = fmaf(c.y, w1.y, tq1);
        tq1 = fmaf(c.z, w1.z, tq1); tq1 = fmaf(c.w, w1.w, tq1);
    }
#pragma unroll
    for (int off = 16; off; off >>= 1) {
        tq0 += __shfl_xor_sync(0xFFFFFFFFu, tq0, off);
        tq1 += __shfl_xor_sync(0xFFFFFFFFu, tq1, off);
    }

#pragma unroll 1
    for (int b = bLo; b <= bHi; b++) {
        __syncthreads();   // protect smem from previous iteration's readers
        for (int idx = tid; idx < NN * 256; idx += THREADS)
            sP4[idx] = gP4[(size_t)b * NN * 256 + idx];
        if (tid < 256) sW2[tid] = w24[tid];
        if (tid < NN)  sTp[tid] = g_termp[b * NN + tid];
        __syncthreads();
        if (bMy != b) continue;

#pragma unroll 1
        for (int pass = 0; pass < 2; pass++) {
            float a0[10], a1[10];
#pragma unroll
            for (int n = 0; n < 10; n++) { a0[n] = 0.f; a1[n] = 0.f; }

            const float4* pb = sP4 + pass * 10 * 256 + half * 128 + lane;
#pragma unroll
            for (int i = 0; i < 4; i++) {
                const float4 w2 = sW2[half * 128 + i * 32 + lane];
#pragma unroll
                for (int n = 0; n < 10; n++) {
                    const float4 p = pb[n * 256 + i * 32];
                    a0[n] = fmaf(fabsf(p.x - qv0[4*i+0]), w2.x, a0[n]);
                    a0[n] = fmaf(p.x, cv0[4*i+0], a0[n]);
                    a1[n] = fmaf(fabsf(p.x - qv1[4*i+0]), w2.x, a1[n]);
                    a1[n] = fmaf(p.x, cv1[4*i+0], a1[n]);
                    a0[n] = fmaf(fabsf(p.y - qv0[4*i+1]), w2.y, a0[n]);
                    a0[n] = fmaf(p.y, cv0[4*i+1], a0[n]);
                    a1[n] = fmaf(fabsf(p.y - qv1[4*i+1]), w2.y, a1[n]);
                    a1[n] = fmaf(p.y, cv1[4*i+1], a1[n]);
                    a0[n] = fmaf(fabsf(p.z - qv0[4*i+2]), w2.z, a0[n]);
                    a0[n] = fmaf(p.z, cv0[4*i+2], a0[n]);
                    a1[n] = fmaf(fabsf(p.z - qv1[4*i+2]), w2.z, a1[n]);
                    a1[n] = fmaf(p.z, cv1[4*i+2], a1[n]);
                    a0[n] = fmaf(fabsf(p.w - qv0[4*i+3]), w2.w, a0[n]);
                    a0[n] = fmaf(p.w, cv0[4*i+3], a0[n]);
                    a1[n] = fmaf(fabsf(p.w - qv1[4*i+3]), w2.w, a1[n]);
                    a1[n] = fmaf(p.w, cv1[4*i+3], a1[n]);
                }
            }

            // deferred reductions: 20 independent butterflies
#pragma unroll
            for (int n = 0; n < 10; n++) {
                float s0 = a0[n], s1 = a1[n];
#pragma unroll
                for (int off = 16; off; off >>= 1) {
                    s0 += __shfl_xor_sync(0xFFFFFFFFu, s0, off);
                    s1 += __shfl_xor_sync(0xFFFFFFFFu, s1, off);
                }
                if (lane == 0) {
                    const int nn = pass * 10 + n;
                    const float extra = (half == 0) ? sTp[nn] + bi : 0.f;
                    sPart[warp * 40 + nn]      = s0 + tq0 + extra;
                    sPart[warp * 40 + 20 + nn] = s1 + tq1 + extra;
                }
            }
        }
    }

    // ---- combine D-halves: out[q, n] = part[half0] + part[half1] ----
    __syncthreads();
    if (tid < PPB * 2 * NN) {                 // 320 outputs
        const int ql = tid / NN;              // local query 0..15
        const int n  = tid - ql * NN;
        const int pp = ql >> 1;               // local pair
        const int wh = ql & 1;                // which query of pair
        const float v = sPart[(pp * 2 + 0) * 40 + wh * 20 + n]
                      + sPart[(pp * 2 + 1) * 40 + wh * 20 + n];
        const int gpair = blockIdx.x * PPB + pp;
        const int b     = gpair / PAIRS_PER_B;
        const int qidx  = (gpair - b * PAIRS_PER_B) * 2 + wh;
        out[((size_t)b * NQ + qidx) * NN + n] = v;
    }
}

// ---------------------------------------------------------------------------
// Launch
// ---------------------------------------------------------------------------
static const int SMEM_BYTES = (NN * DD + 1024 + 32 + WARPS * 40) * (int)sizeof(float); // 88,704 B

extern "C" void kernel_launch(void* const* d_in, const int* in_sizes, int n_in,
                              void* d_out, int out_size)
{
    const float* emb    = (const float*)d_in[0];
    const float* weight = (const float*)d_in[1];
    const float* bias   = (const float*)d_in[2];
    float* out          = (float*)d_out;

    cudaFuncSetAttribute(relnet_kernel,
                         cudaFuncAttributeMaxDynamicSharedMemorySize, SMEM_BYTES);

    proto_kernel<<<BB * NN, 256>>>(emb, weight);
    relnet_kernel<<<GRID, THREADS, SMEM_BYTES>>>(emb, weight, bias, out);
}

// round 10
// speedup vs baseline: 1.4031x; 1.0992x over previous
#include <cuda_runtime.h>

// Problem constants (fixed by setup_inputs): B=8, N=20, K=5, Q=15, D=1024
#define BB     8
#define NN     20
#define KSUP   5
#define QQ     15
#define DD     1024
#define ROWS   (KSUP + QQ)        // 20 rows per (b,n)
#define NQ     (NN * QQ)          // 300 queries per batch
#define NQTOT  (BB * NQ)          // 2400 queries total
#define WARPS  16
#define THREADS 512
#define GRID   (NQTOT / WARPS)    // 150 blocks, 1 query/warp, single wave

// Scratch (device globals — no allocation allowed)
__device__ float g_proto[BB * NN * DD];   // 640 KB, L2-resident
__device__ float g_termp[BB * NN];

// ---------------------------------------------------------------------------
// K1: proto[b,n,:] = mean_j support, term_p[b,n] = proto . w0  (computed ONCE)
// ---------------------------------------------------------------------------
__global__ __launch_bounds__(256) void proto_kernel(
    const float* __restrict__ emb, const float* __restrict__ weight)
{
    int bn = blockIdx.x;             // b*20 + n
    int t  = threadIdx.x;            // float4 index 0..255
    const float4* base = reinterpret_cast<const float4*>(emb) + (size_t)bn * ROWS * 256;

    float4 s = base[t];
#pragma unroll
    for (int j = 1; j < KSUP; j++) {
        float4 v = base[j * 256 + t];
        s.x += v.x; s.y += v.y; s.z += v.z; s.w += v.w;
    }
    s.x *= 0.2f; s.y *= 0.2f; s.z *= 0.2f; s.w *= 0.2f;
    reinterpret_cast<float4*>(g_proto)[(size_t)bn * 256 + t] = s;

    float4 w0 = reinterpret_cast<const float4*>(weight)[t];
    float tp = s.x * w0.x + s.y * w0.y + s.z * w0.z + s.w * w0.w;
#pragma unroll
    for (int off = 16; off; off >>= 1) tp += __shfl_xor_sync(0xFFFFFFFFu, tp, off);

    __shared__ float red[8];
    if ((t & 31) == 0) red[t >> 5] = tp;
    __syncthreads();
    if (t == 0) {
        float r = 0.f;
#pragma unroll
        for (int w = 0; w < 8; w++) r += red[w];
        g_termp[bn] = r;
    }
}

// ---------------------------------------------------------------------------
// Main: 150 blocks x 512 threads (16 warps), 1 block/SM, single wave,
// ZERO shared memory, ZERO block-level syncs. Each warp owns one query;
// proto is read directly via LDG (L2-resident, L1-cached: 80KB/SM working
// set fits the 228KB L1 with no smem carveout). This deletes the smem fill
// (~1000 instrs/warp) and all barrier phases that capped previous rounds.
// All 20 n-accumulators in registers (two passes of 10); deferred butterflies.
// ---------------------------------------------------------------------------
__global__ __launch_bounds__(THREADS, 1) void relnet_kernel(
    const float* __restrict__ emb,
    const float* __restrict__ weight,
    const float* __restrict__ bias,
    float* __restrict__ out)
{
    const int tid  = threadIdx.x;
    const int lane = tid & 31;
    const int warp = tid >> 5;

    const int g   = blockIdx.x * WARPS + warp;   // global query id 0..2399
    const int bMy = g / NQ;
    const int q   = g - bMy * NQ;                // query idx within batch

    const float4* emb4 = reinterpret_cast<const float4*>(emb);
    const float4* w14  = reinterpret_cast<const float4*>(weight) + 1 * 256;
    const float4* w24  = reinterpret_cast<const float4*>(weight) + 2 * 256;
    const float4* w34  = reinterpret_cast<const float4*>(weight) + 3 * 256;
    const float4* pf   = reinterpret_cast<const float4*>(g_proto) + (size_t)bMy * NN * 256;
    const float bi = bias[0];

    // ---- per-warp query registers: q and q*w3; fold term_q ----
    const int qrow = (bMy * NN + q / QQ) * ROWS + KSUP + q % QQ;
    const float4* r = emb4 + (size_t)qrow * 256;

    float qv[32], cv[32];
    float tq = 0.f;
#pragma unroll
    for (int i = 0; i < 8; i++) {
        const int idx = i * 32 + lane;
        float4 a  = __ldg(r + idx);
        float4 w3 = __ldg(w34 + idx);
        float4 w1 = __ldg(w14 + idx);
        qv[4*i+0] = a.x; qv[4*i+1] = a.y; qv[4*i+2] = a.z; qv[4*i+3] = a.w;
        cv[4*i+0] = a.x * w3.x; cv[4*i+1] = a.y * w3.y;
        cv[4*i+2] = a.z * w3.z; cv[4*i+3] = a.w * w3.w;
        tq = fmaf(a.x, w1.x, tq); tq = fmaf(a.y, w1.y, tq);
        tq = fmaf(a.z, w1.z, tq); tq = fmaf(a.w, w1.w, tq);
    }
#pragma unroll
    for (int off = 16; off; off >>= 1) tq += __shfl_xor_sync(0xFFFFFFFFu, tq, off);

    // term_p for this batch, lane-spread (lane n holds termp[n])
    float tpv = (lane < NN) ? __ldg(&g_termp[bMy * NN + lane]) : 0.f;

    float* o = out + ((size_t)bMy * NQ + q) * NN;

#pragma unroll 1
    for (int pass = 0; pass < 2; pass++) {
        float acc[10];
#pragma unroll
        for (int n = 0; n < 10; n++) acc[n] = 0.f;

        const float4* pb = pf + pass * 10 * 256 + lane;
#pragma unroll
        for (int i = 0; i < 8; i++) {
            const float4 w2 = __ldg(w24 + i * 32 + lane);
#pragma unroll
            for (int n = 0; n < 10; n++) {
                const float4 p = __ldg(pb + n * 256 + i * 32);
                acc[n] = fmaf(fabsf(p.x - qv[4*i+0]), w2.x, acc[n]);
                acc[n] = fmaf(p.x, cv[4*i+0], acc[n]);
                acc[n] = fmaf(fabsf(p.y - qv[4*i+1]), w2.y, acc[n]);
                acc[n] = fmaf(p.y, cv[4*i+1], acc[n]);
                acc[n] = fmaf(fabsf(p.z - qv[4*i+2]), w2.z, acc[n]);
                acc[n] = fmaf(p.z, cv[4*i+2], acc[n]);
                acc[n] = fmaf(fabsf(p.w - qv[4*i+3]), w2.w, acc[n]);
                acc[n] = fmaf(p.w, cv[4*i+3], acc[n]);
            }
        }

        // deferred reductions: 10 independent butterflies
#pragma unroll
        for (int n = 0; n < 10; n++) {
            float s = acc[n];
#pragma unroll
            for (int off = 16; off; off >>= 1)
                s += __shfl_xor_sync(0xFFFFFFFFu, s, off);
            acc[n] = s;
        }
#pragma unroll
        for (int n = 0; n < 10; n++) {
            const int nn = pass * 10 + n;
            const float tp = __shfl_sync(0xFFFFFFFFu, tpv, nn);
            if (lane == 0) o[nn] = acc[n] + tp + tq + bi;
        }
    }
}

// ---------------------------------------------------------------------------
// Launch
// ---------------------------------------------------------------------------
extern "C" void kernel_launch(void* const* d_in, const int* in_sizes, int n_in,
                              void* d_out, int out_size)
{
    const float* emb    = (const float*)d_in[0];
    const float* weight = (const float*)d_in[1];
    const float* bias   = (const float*)d_in[2];
    float* out          = (float*)d_out;

    proto_kernel<<<BB * NN, 256>>>(emb, weight);
    relnet_kernel<<<GRID, THREADS>>>(emb, weight, bias, out);
}

// round 11
// speedup vs baseline: 1.7178x; 1.2243x over previous
#include <cuda_runtime.h>

// Problem constants (fixed by setup_inputs): B=8, N=20, K=5, Q=15, D=1024
#define BB     8
#define NN     20
#define KSUP   5
#define QQ     15
#define DD     1024
#define ROWS   (KSUP + QQ)        // 20 rows per (b,n)
#define NQ     (NN * QQ)          // 300 queries per batch
#define WARPS  16
#define THREADS 512
#define BPB    19                 // blocks per batch (19*16=304 >= 300 queries)
#define GRID   (BB * BPB)         // 152 blocks == GB300 SM count, single wave

// Scratch (device globals — no allocation allowed)
__device__ float g_proto[BB * NN * DD];   // 640 KB, L2-resident
__device__ float g_termp[BB * NN];

// ---------------------------------------------------------------------------
// K1: proto[b,n,:] = mean_j support, term_p[b,n] = proto . w0  (computed ONCE)
// ---------------------------------------------------------------------------
__global__ __launch_bounds__(256) void proto_kernel(
    const float* __restrict__ emb, const float* __restrict__ weight)
{
    int bn = blockIdx.x;             // b*20 + n
    int t  = threadIdx.x;            // float4 index 0..255
    const float4* base = reinterpret_cast<const float4*>(emb) + (size_t)bn * ROWS * 256;

    float4 s = base[t];
#pragma unroll
    for (int j = 1; j < KSUP; j++) {
        float4 v = base[j * 256 + t];
        s.x += v.x; s.y += v.y; s.z += v.z; s.w += v.w;
    }
    s.x *= 0.2f; s.y *= 0.2f; s.z *= 0.2f; s.w *= 0.2f;
    reinterpret_cast<float4*>(g_proto)[(size_t)bn * 256 + t] = s;

    float4 w0 = reinterpret_cast<const float4*>(weight)[t];
    float tp = s.x * w0.x + s.y * w0.y + s.z * w0.z + s.w * w0.w;
#pragma unroll
    for (int off = 16; off; off >>= 1) tp += __shfl_xor_sync(0xFFFFFFFFu, tp, off);

    __shared__ float red[8];
    if ((t & 31) == 0) red[t >> 5] = tp;
    __syncthreads();
    if (t == 0) {
        float r = 0.f;
#pragma unroll
        for (int w = 0; w < 8; w++) r += red[w];
        g_termp[bn] = r;
    }
}

// ---------------------------------------------------------------------------
// Main: 152 blocks (= SM count) x 512 threads, one batch per block, single
// wave, ONE sync. Each warp owns one query (full D in registers: q, q*w3).
// Hot loop: n-blocks of 4 with DOUBLE-BUFFERED LDS prefetch — the 5 loads of
// i-batch i+1 are issued before the 48 FMA ops of batch i, hiding the 29-cyc
// LDS latency inside the warp. ~120 live regs, no spills at the 128 cap.
// ---------------------------------------------------------------------------
__global__ __launch_bounds__(THREADS, 1) void relnet_kernel(
    const float* __restrict__ emb,
    const float* __restrict__ weight,
    const float* __restrict__ bias,
    float* __restrict__ out)
{
    extern __shared__ float smem[];
    float4* sP4 = reinterpret_cast<float4*>(smem);               // 20*256 f4 = 81920 B
    float4* sW2 = reinterpret_cast<float4*>(smem + NN * DD);     // 256 f4    =  4096 B
    float*  sTp = smem + NN * DD + 1024;                         // 20 floats

    const int tid  = threadIdx.x;
    const int lane = tid & 31;
    const int warp = tid >> 5;

    const int b   = blockIdx.x / BPB;                 // batch
    const int blk = blockIdx.x - b * BPB;             // 0..18
    const int q   = blk * WARPS + warp;               // 0..303
    const bool active = (q < NQ);

    const float4* emb4 = reinterpret_cast<const float4*>(emb);
    const float4* w14  = reinterpret_cast<const float4*>(weight) + 1 * 256;
    const float4* w24  = reinterpret_cast<const float4*>(weight) + 2 * 256;
    const float4* w34  = reinterpret_cast<const float4*>(weight) + 3 * 256;
    const float4* gP4  = reinterpret_cast<const float4*>(g_proto);
    const float bi = bias[0];

    // ---- fill: proto tile for THIS batch, w2, termp (10 f4 per thread) ----
#pragma unroll
    for (int k = 0; k < 10; k++) {
        const int idx = k * THREADS + tid;
        sP4[idx] = gP4[(size_t)b * NN * 256 + idx];
    }
    if (tid < 256) sW2[tid] = w24[tid];
    if (tid < NN)  sTp[tid] = g_termp[b * NN + tid];
    __syncthreads();

    if (!active) return;

    // ---- per-warp query registers: q and q*w3; fold term_q ----
    const int qrow = (b * NN + q / QQ) * ROWS + KSUP + q % QQ;
    const float4* r = emb4 + (size_t)qrow * 256;

    float qv[32], cv[32];
    float tq = 0.f;
#pragma unroll
    for (int i = 0; i < 8; i++) {
        const int idx = i * 32 + lane;
        float4 a  = r[idx];
        float4 w3 = w34[idx];
        float4 w1 = w14[idx];
        qv[4*i+0] = a.x; qv[4*i+1] = a.y; qv[4*i+2] = a.z; qv[4*i+3] = a.w;
        cv[4*i+0] = a.x * w3.x; cv[4*i+1] = a.y * w3.y;
        cv[4*i+2] = a.z * w3.z; cv[4*i+3] = a.w * w3.w;
        tq = fmaf(a.x, w1.x, tq); tq = fmaf(a.y, w1.y, tq);
        tq = fmaf(a.z, w1.z, tq); tq = fmaf(a.w, w1.w, tq);
    }
#pragma unroll
    for (int off = 16; off; off >>= 1) tq += __shfl_xor_sync(0xFFFFFFFFu, tq, off);

    float* o = out + ((size_t)b * NQ + q) * NN;

    // ---- hot loop: 5 n-blocks of 4, double-buffered LDS prefetch over i ----
#pragma unroll 1
    for (int nb = 0; nb < 5; nb++) {
        const float4* pb = sP4 + nb * 4 * 256 + lane;

        float acc[4] = {0.f, 0.f, 0.f, 0.f};
        float4 pc[4], w2c;
        w2c = sW2[lane];
#pragma unroll
        for (int n = 0; n < 4; n++) pc[n] = pb[n * 256];

#pragma unroll
        for (int i = 0; i < 8; i++) {
            float4 pn[4], w2n;
            if (i < 7) {                       // prefetch batch i+1
                w2n = sW2[(i + 1) * 32 + lane];
#pragma unroll
                for (int n = 0; n < 4; n++) pn[n] = pb[n * 256 + (i + 1) * 32];
            }
#pragma unroll
            for (int n = 0; n < 4; n++) {
                const float4 p = pc[n];
                acc[n] = fmaf(fabsf(p.x - qv[4*i+0]), w2c.x, acc[n]);
                acc[n] = fmaf(p.x, cv[4*i+0], acc[n]);
                acc[n] = fmaf(fabsf(p.y - qv[4*i+1]), w2c.y, acc[n]);
                acc[n] = fmaf(p.y, cv[4*i+1], acc[n]);
                acc[n] = fmaf(fabsf(p.z - qv[4*i+2]), w2c.z, acc[n]);
                acc[n] = fmaf(p.z, cv[4*i+2], acc[n]);
                acc[n] = fmaf(fabsf(p.w - qv[4*i+3]), w2c.w, acc[n]);
                acc[n] = fmaf(p.w, cv[4*i+3], acc[n]);
            }
            if (i < 7) {
#pragma unroll
                for (int n = 0; n < 4; n++) pc[n] = pn[n];
                w2c = w2n;
            }
        }

        // deferred reductions: 4 independent butterflies per n-block
#pragma unroll
        for (int n = 0; n < 4; n++) {
            float s = acc[n];
#pragma unroll
            for (int off = 16; off; off >>= 1)
                s += __shfl_xor_sync(0xFFFFFFFFu, s, off);
            acc[n] = s;
        }
        if (lane == 0) {
#pragma unroll
            for (int n = 0; n < 4; n++) {
                const int nn = nb * 4 + n;
                o[nn] = acc[n] + sTp[nn] + tq + bi;
            }
        }
    }
}

// ---------------------------------------------------------------------------
// Launch
// ---------------------------------------------------------------------------
static const int SMEM_BYTES = (NN * DD + 1024 + 32) * (int)sizeof(float); // 86,144 B

extern "C" void kernel_launch(void* const* d_in, const int* in_sizes, int n_in,
                              void* d_out, int out_size)
{
    const float* emb    = (const float*)d_in[0];
    const float* weight = (const float*)d_in[1];
    const float* bias   = (const float*)d_in[2];
    float* out          = (float*)d_out;

    cudaFuncSetAttribute(relnet_kernel,
                         cudaFuncAttributeMaxDynamicSharedMemorySize, SMEM_BYTES);

    proto_kernel<<<BB * NN, 256>>>(emb, weight);
    relnet_kernel<<<GRID, THREADS, SMEM_BYTES>>>(emb, weight, bias, out);
}